// round 17
// baseline (speedup 1.0000x reference)
#include <cuda_runtime.h>

#define NB 64
#define NT 256
#define BT (NB*NT)
#define BNS 0.9999950000374997f

__constant__ int c_s2j[25] = {0,1,2,3,20, 4,5,6,7,21,22, 8,9,10,11,23,24, 12,13,14,15, 16,17,18,19};
__constant__ int c_gstart[5] = {0,5,11,17,21};
__constant__ int c_gn[5]     = {5,6,6,4,4};

__device__ float g_adj[5][6][6];
__device__ float g_Z [BT*25*64];
__device__ float g_Y1[BT*25*64];
__device__ float g_Y2[BT*25*128];
__device__ float g_Y3[BT*25*64];
__device__ float g_psum[5*64*16*64];
__device__ float g_loss[5*64];
__device__ float g_sb3[5*64];
__device__ float g_swf1[5*64*64], g_swf2[5*128*64];
__device__ float g_cst1[5*64],  g_bb0_1[5*64],  g_bb2_1[5*64];
__device__ float g_cst2[5*128], g_bb0_2[5*128], g_bb2_2[5*128];
__device__ float g_cst3[5*64];
__device__ float g_zero[640];
__device__ float4 g_sw3i[10240];
__device__ float4 g_rw2i[10240];
__device__ float4 g_rw3i[10240];
__device__ float4 g_tw1i[15360];
__device__ float4 g_tw2i[30720];
__device__ float4 g_tw3i[15360];

__device__ __forceinline__ unsigned long long bc2(float x){
    unsigned long long r; unsigned u = __float_as_uint(x);
    asm("mov.b64 %0, {%1, %1};" : "=l"(r) : "r"(u));
    return r;
}
__device__ __forceinline__ unsigned long long pk2(float a, float b){
    unsigned long long r;
    asm("mov.b64 %0, {%1, %2};" : "=l"(r) : "r"(__float_as_uint(a)), "r"(__float_as_uint(b)));
    return r;
}
__device__ __forceinline__ void ffma2(unsigned long long& c, unsigned long long a, unsigned long long b){
    asm("fma.rn.f32x2 %0, %1, %2, %0;" : "+l"(c) : "l"(a), "l"(b));
}
__device__ __forceinline__ void unpk(unsigned long long v, float& lo, float& hi){
    unsigned a,b; asm("mov.b64 {%0, %1}, %2;" : "=r"(a), "=r"(b) : "l"(v));
    lo = __uint_as_float(a); hi = __uint_as_float(b);
}

// fold sw1/sw2 (the 3-subset sum) once; composites then read 2 loads/k instead of 6
__global__ __launch_bounds__(256) void k_prep0(const float* __restrict__ sw1,
                                               const float* __restrict__ sw2)
{
    int gt  = blockIdx.x*blockDim.x + threadIdx.x;
    int NTH = gridDim.x*blockDim.x;
    for (int i=gt;i<5*4096;i+=NTH){
        int g=i/4096, r=i%4096, c=r/64, k=r%64;
        const float* w = sw1 + g*192*64;
        g_swf1[i] = w[c*64+k] + w[(64+c)*64+k] + w[(128+c)*64+k];
    }
    for (int i=gt;i<5*8192;i+=NTH){
        int g=i/8192, r=i%8192, c=r/64, k=r%64;
        const float* w = sw2 + g*384*64;
        g_swf2[i] = w[c*64+k] + w[(128+c)*64+k] + w[(256+c)*64+k];
    }
}

__global__ __launch_bounds__(256) void k_prep(
    const float* __restrict__ sw1, const float* __restrict__ sb1,
    const float* __restrict__ tw1, const float* __restrict__ tb1,
    const float* __restrict__ rw2, const float* __restrict__ rb2,
    const float* __restrict__ rg2, const float* __restrict__ rbb2,
    const float* __restrict__ sw2, const float* __restrict__ sb2,
    const float* __restrict__ tw2, const float* __restrict__ tb2,
    const float* __restrict__ rw3, const float* __restrict__ rb3,
    const float* __restrict__ rg3, const float* __restrict__ rbb3,
    const float* __restrict__ sw3, const float* __restrict__ sb3,
    const float* __restrict__ tw3, const float* __restrict__ tb3)
{
    int gt  = blockIdx.x*blockDim.x + threadIdx.x;
    int NTH = gridDim.x*blockDim.x;

    for (int e=gt;e<15360;e+=NTH){
        int g=e/3072, r=e%3072, kt=r/1024, r2=r%1024, kk2=r2/32, q=r2%32, jp=q/8, tx=q%8;
        int oa=tx+16*jp, ob=oa+8, k0=2*kk2;
        float v0=0.f,v1=0.f,v2=0.f,v3=0.f;
        const float* wf = g_swf1 + g*4096;
        for (int c=0;c<64;c++){
            float s0 = wf[c*64+k0];
            float s1 = wf[c*64+k0+1];
            float wa = tw1[((g*64+oa)*64+c)*3+kt];
            float wb = tw1[((g*64+ob)*64+c)*3+kt];
            v0=fmaf(wa,s0,v0); v1=fmaf(wb,s0,v1); v2=fmaf(wa,s1,v2); v3=fmaf(wb,s1,v3);
        }
        g_tw1i[e]=make_float4(v0,v1,v2,v3);
    }
    for (int e=gt;e<15360;e+=NTH){
        int g=e/3072, r=e%3072, kt=r/1024, r2=r%1024, kk2=r2/32, q=r2%32, jp=q/8, tx=q%8;
        int oa=tx+16*jp, ob=oa+8, k0=2*kk2;
        g_tw3i[e]=make_float4(tw3[((g*64+oa)*64+k0)*3+kt],   tw3[((g*64+ob)*64+k0)*3+kt],
                              tw3[((g*64+oa)*64+k0+1)*3+kt], tw3[((g*64+ob)*64+k0+1)*3+kt]);
    }
    for (int e=gt;e<30720;e+=NTH){
        int g=e/6144, r=e%6144, kt=r/2048, r2=r%2048, kk2=r2/64, q=r2%64, jp=q/16, tx=q%16;
        int oa=tx+32*jp, ob=oa+16, k0=2*kk2;
        float v0=0.f,v1=0.f,v2=0.f,v3=0.f;
        const float* wf = g_swf2 + g*8192;
        for (int c=0;c<128;c++){
            float s0 = wf[c*64+k0];
            float s1 = wf[c*64+k0+1];
            float wa = tw2[((g*128+oa)*128+c)*3+kt];
            float wb = tw2[((g*128+ob)*128+c)*3+kt];
            v0=fmaf(wa,s0,v0); v1=fmaf(wb,s0,v1); v2=fmaf(wa,s1,v2); v3=fmaf(wb,s1,v3);
        }
        g_tw2i[e]=make_float4(v0,v1,v2,v3);
    }
    for (int e=gt;e<10240;e+=NTH){
        int g=e/2048, r=e%2048, kk2=r/32, q=r%32, jp=q/8, tx=q%8;
        int oa=tx+16*jp, ob=oa+8, k0=2*kk2;
        const float* w = sw3 + g*192*128;
        #define S3(o,c) (w[(o)*128+(c)] + w[(64+(o))*128+(c)] + w[(128+(o))*128+(c)])
        g_sw3i[e] = make_float4(S3(oa,k0), S3(ob,k0), S3(oa,k0+1), S3(ob,k0+1));
        #undef S3
    }
    for (int e=gt;e<10240;e+=NTH){
        int g=e/2048, r=e%2048, kk2=r/64, q=r%64, jp=q/16, tx=q%16;
        int oa=tx+32*jp, ob=oa+16, k0=2*kk2;
        const float* w = rw2 + g*8192;
        float sa_=rg2[g*128+oa]*BNS, sb_=rg2[g*128+ob]*BNS;
        g_rw2i[e] = make_float4(w[oa*64+k0]*sa_, w[ob*64+k0]*sb_, w[oa*64+k0+1]*sa_, w[ob*64+k0+1]*sb_);
    }
    for (int e=gt;e<10240;e+=NTH){
        int g=e/2048, r=e%2048, kk2=r/32, q=r%32, jp=q/8, tx=q%8;
        int oa=tx+16*jp, ob=oa+8, k0=2*kk2;
        const float* w = rw3 + g*8192;
        float sa_=rg3[g*64+oa]*BNS, sb_=rg3[g*64+ob]*BNS;
        g_rw3i[e] = make_float4(w[oa*128+k0]*sa_, w[ob*128+k0]*sb_, w[oa*128+k0+1]*sa_, w[ob*128+k0+1]*sb_);
    }
    for (int i=gt;i<5*64;i+=NTH){
        int g=i/64, o=i%64;
        float b0=0.f,b1=0.f,b2=0.f;
        for (int c=0;c<64;c++){
            float sb = sb1[g*192+c]+sb1[g*192+64+c]+sb1[g*192+128+c];
            b0=fmaf(tw1[((g*64+o)*64+c)*3+0],sb,b0);
            b1=fmaf(tw1[((g*64+o)*64+c)*3+1],sb,b1);
            b2=fmaf(tw1[((g*64+o)*64+c)*3+2],sb,b2);
        }
        g_cst1[i]=tb1[i]+b0+b1+b2;
        g_bb0_1[i]=b0; g_bb2_1[i]=b2;
        const float* s3=sb3+g*192;
        g_sb3[i]=s3[o]+s3[64+o]+s3[128+o];
        g_cst3[i]=tb3[i]+rb3[i]*rg3[i]*BNS+rbb3[i];
    }
    for (int i=gt;i<5*128;i+=NTH){
        int g=i/128, o=i%128;
        float b0=0.f,b1=0.f,b2=0.f;
        for (int c=0;c<128;c++){
            float sb = sb2[g*384+c]+sb2[g*384+128+c]+sb2[g*384+256+c];
            b0=fmaf(tw2[((g*128+o)*128+c)*3+0],sb,b0);
            b1=fmaf(tw2[((g*128+o)*128+c)*3+1],sb,b1);
            b2=fmaf(tw2[((g*128+o)*128+c)*3+2],sb,b2);
        }
        g_cst2[i]=tb2[i]+rb2[i]*rg2[i]*BNS+rbb2[i]+b0+b1+b2;
        g_bb0_2[i]=b0; g_bb2_2[i]=b2;
    }
    for (int i=gt;i<640;i+=NTH) g_zero[i]=0.f;
    if (gt==0){
        double fa[25][25];
        for (int i=0;i<25;i++) for (int j=0;j<25;j++) fa[i][j]=0.0;
        const int E[24][2]={{3,2},{2,20},{20,1},{1,0},{20,4},{4,5},{5,6},{6,22},
                            {6,7},{7,21},{20,8},{8,9},{9,10},{10,24},{10,11},{11,23},
                            {0,12},{12,13},{13,14},{14,15},{0,16},{16,17},{17,18},{18,19}};
        for (int k=0;k<24;k++){
            int i=E[k][0]-1, j=E[k][1]-1;
            fa[i][j]=1.0; fa[j][i]=1.0;
        }
        for (int i=0;i<25;i++) fa[i][i]+=1.0;
        for (int i=0;i<25;i++){
            double d=0; for (int j=0;j<25;j++) d+=fa[i][j];
            if (d==0.0) d=1.0;
            for (int j=0;j<25;j++) fa[i][j]/=d;
        }
        for (int g=0;g<5;g++){
            int n=c_gn[g];
            int js[6]; for (int u=0;u<n;u++) js[u]=c_s2j[c_gstart[g]+u];
            double sa[6][6];
            for (int u=0;u<n;u++) for (int v=0;v<n;v++) sa[u][v]=fa[js[u]][js[v]];
            for (int u=0;u<n;u++) sa[u][u]+=1.0;
            double dg[6];
            for (int u=0;u<n;u++){ double d=0; for (int v=0;v<n;v++) d+=sa[u][v]; dg[u]=d; }
            for (int node=1;node<n;node++)
                if (dg[node]==1.0){ sa[0][node]=1.0; sa[node][0]=1.0; }
            for (int u=0;u<6;u++) for (int v=0;v<6;v++){
                float val=0.f;
                if (u<n && v<n){
                    double d=0; for (int w=0;w<n;w++) d+=sa[u][w];
                    if (d==0.0) d=1.0;
                    val=(float)(sa[u][v]/d);
                }
                g_adj[g][u][v]=val;
            }
        }
    }
}

template<int CT,int NR>
__device__ __forceinline__ void gemm_kk4(unsigned long long (&acc)[NR][4],
                                         const float4* aPtr, int aStride,
                                         const ulonglong2* wPtr)
{
    float4 a[NR];
    #pragma unroll
    for (int i=0;i<NR;++i) a[i] = aPtr[aStride*i];
    #pragma unroll
    for (int h=0;h<2;++h){
        ulonglong2 w0 = wPtr[h*4*CT + 0*CT];
        ulonglong2 w1 = wPtr[h*4*CT + 1*CT];
        ulonglong2 w2 = wPtr[h*4*CT + 2*CT];
        ulonglong2 w3 = wPtr[h*4*CT + 3*CT];
        #pragma unroll
        for (int i=0;i<NR;++i){
            unsigned long long alo = bc2(h ? a[i].z : a[i].x);
            unsigned long long ahi = bc2(h ? a[i].w : a[i].y);
            ffma2(acc[i][0], alo, w0.x);
            ffma2(acc[i][1], alo, w1.x);
            ffma2(acc[i][2], alo, w2.x);
            ffma2(acc[i][3], alo, w3.x);
            ffma2(acc[i][0], ahi, w0.y);
            ffma2(acc[i][1], ahi, w1.y);
            ffma2(acc[i][2], ahi, w2.y);
            ffma2(acc[i][3], ahi, w3.y);
        }
    }
}

// ---- Layer-3 GCN body: TBL=16, 128 threads, 4 CTAs/SM ----
template<int N>
__device__ __forceinline__ void gcn3_body(const float* __restrict__ Y,
                                          float* __restrict__ Z,
                                          const float4* __restrict__ Wi,
                                          const float* __restrict__ Bv,
                                          int g, float* sm)
{
    constexpr int CT = 8;
    float4* sA4 = (float4*)sm;
    float4* sW4 = sA4 + 16*N*17;
    const ulonglong2* sWl = (const ulonglong2*)sW4;
    __shared__ float sAdj[6][6];

    const int gs0 = c_gstart[g];
    const int bt0 = blockIdx.x * 16;
    const int tid = threadIdx.x;
    if (tid < 36) sAdj[tid/6][tid%6] = g_adj[g][tid/6][tid%6];

    const int ty = tid / CT, tx = tid % CT;
    unsigned long long acc[N][4];
    #pragma unroll
    for (int jp=0;jp<4;++jp){
        int oa = tx + 16*jp;
        unsigned long long b2 = pk2(Bv[g*64+oa], Bv[g*64+oa+8]);
        #pragma unroll
        for (int i=0;i<N;++i) acc[i][jp]=b2;
    }
    const float4* Wg = Wi + (size_t)g*2048;

    for (int ph=0; ph<2; ++ph){
        __syncthreads();
        for (int p=tid; p<16*16; p+=128){
            int c4l = p % 16, t = p / 16;
            int c4 = ph*16 + c4l;
            const float4* yp = (const float4*)(Y + ((size_t)(bt0+t)*25 + gs0)*128) + c4;
            float4 yv[N];
            #pragma unroll
            for (int vv=0; vv<N; ++vv) yv[vv] = yp[(size_t)vv*32];
            #pragma unroll
            for (int uu=0; uu<N; ++uu){
                float4 v = make_float4(0.f,0.f,0.f,0.f);
                #pragma unroll
                for (int vv=0; vv<N; ++vv){
                    float av = sAdj[uu][vv];
                    v.x += av*yv[vv].x; v.y += av*yv[vv].y;
                    v.z += av*yv[vv].z; v.w += av*yv[vv].w;
                }
                sA4[(t*N+uu)*17 + c4l] = v;
            }
        }
        for (int p=tid; p<1024; p+=128) sW4[p] = Wg[ph*1024 + p];
        __syncthreads();
        #pragma unroll 8
        for (int kk4l=0;kk4l<16;++kk4l)
            gemm_kk4<CT,N>(acc, sA4 + ty*17 + kk4l, 16*17, sWl + 2*kk4l*4*CT + tx);
    }

    #pragma unroll
    for (int i=0;i<N;++i){
        int r = ty+16*i, t = r/N, u = r%N;
        float* zp = Z + ((size_t)(bt0+t)*25 + gs0+u)*64;
        #pragma unroll
        for (int jp=0;jp<4;++jp){
            float lo,hi; unpk(acc[i][jp], lo, hi);
            int oa = tx + 16*jp;
            zp[oa] = lo; zp[oa+8] = hi;
        }
    }
}

__global__ __launch_bounds__(128,4) void k_gcn3(const float* __restrict__ Y,
                                                float* __restrict__ Z,
                                                const float4* __restrict__ Wi,
                                                const float* __restrict__ Bv)
{
    extern __shared__ float sm[];
    int g = blockIdx.y;
    if (g == 0)      gcn3_body<5>(Y,Z,Wi,Bv,0,sm);
    else if (g <= 2) gcn3_body<6>(Y,Z,Wi,Bv,g,sm);
    else             gcn3_body<4>(Y,Z,Wi,Bv,g,sm);
}

// ---- tconv body (N real slots, TBL time rows per block) ----
template<int COUT,int CRES,int MODE,int GCONV,int EMB,int PSUM,int TBL,int N>
__device__ __forceinline__ void tconv_body(const float* __restrict__ Zin,
             const float* __restrict__ Yres, float* __restrict__ Yout,
             const float4* __restrict__ TWi, const float4* __restrict__ RWi,
             const float* __restrict__ CST, const float* __restrict__ BB0,
             const float* __restrict__ BB2,
             const float* __restrict__ GS, const float* __restrict__ BB,
             const float* __restrict__ EW, const float* __restrict__ EB,
             int g, float* sm)
{
    constexpr int CT  = COUT/8;
    constexpr int TH  = CT*TBL;
    constexpr int C4  = 16;
    constexpr int PRZ = 17;
    constexpr int WKT = 32*4*CT;
    constexpr int SBUF4 = (TBL+2)*N*PRZ;
    float4* sB4 = (float4*)sm;
    float4* sW4 = sB4 + SBUF4;
    const ulonglong2* sWl = (const ulonglong2*)sW4;
    float* sX  = (float*)(sW4 + WKT);
    float* sEW = sX + (TBL+2)*N*3;
    float* sEB = sEW + 192;
    __shared__ float sAdj[6][6];

    const int gs0 = c_gstart[g];
    const int bt0 = blockIdx.x * TBL;
    const int t0  = bt0 & (NT-1);
    const int tid = threadIdx.x, ty = tid/CT, tx = tid%CT;

    if (GCONV){
        if (tid < 36) sAdj[tid/6][tid%6] = g_adj[g][tid/6][tid%6];
    }
    if (EMB){
        for (int p=tid; p<192; p+=TH) sEW[p] = EW[p];
        for (int p=tid; p<64;  p+=TH) sEB[p] = EB[p];
        for (int p=tid; p<(TBL+2)*N; p+=TH){
            int u = p % N, hb = p / N;
            int t = t0 + hb - 1;
            float x0=0.f,x1=0.f,x2=0.f;
            if (t >= 0 && t < NT){
                int j = c_s2j[gs0+u];
                const float* xp = Zin + ((size_t)(bt0+hb-1)*25 + j)*3;
                x0=xp[0]; x1=xp[1]; x2=xp[2];
            }
            sX[p*3+0]=x0; sX[p*3+1]=x1; sX[p*3+2]=x2;
        }
    }
    if (GCONV || EMB) __syncthreads();

    if (EMB){
        for (int p=tid; p<(TBL+2)*C4; p+=TH){
            int c4 = p % C4, hb = p / C4;
            int t = t0 + hb - 1;
            bool valid = (t >= 0 && t < NT);
            float h[N][4];
            if (valid){
                #pragma unroll
                for (int vv=0; vv<N; ++vv){
                    const float* xr = sX + (hb*N+vv)*3;
                    float x0=xr[0], x1=xr[1], x2=xr[2];
                    #pragma unroll
                    for (int cc=0;cc<4;++cc){
                        int c = c4*4+cc;
                        h[vv][cc] = fmaf(x2, sEW[c*3+2],
                                    fmaf(x1, sEW[c*3+1],
                                    fmaf(x0, sEW[c*3+0], sEB[c])));
                    }
                }
            }
            #pragma unroll
            for (int uu=0; uu<N; ++uu){
                float4 v = make_float4(0.f,0.f,0.f,0.f);
                if (valid){
                    #pragma unroll
                    for (int vv=0; vv<N; ++vv){
                        float av = sAdj[uu][vv];
                        v.x = fmaf(av,h[vv][0],v.x);
                        v.y = fmaf(av,h[vv][1],v.y);
                        v.z = fmaf(av,h[vv][2],v.z);
                        v.w = fmaf(av,h[vv][3],v.w);
                    }
                }
                sB4[(hb*N+uu)*PRZ + c4] = v;
            }
        }
    } else if (GCONV){
        for (int p=tid; p<(TBL+2)*C4; p+=TH){
            int c4 = p % C4, hb = p / C4;
            int t = t0 + hb - 1;
            bool valid = (t >= 0 && t < NT);
            float4 yv[N];
            if (valid){
                const float4* yp = (const float4*)(Zin + ((size_t)(bt0+hb-1)*25 + gs0)*64) + c4;
                #pragma unroll
                for (int vv=0; vv<N; ++vv) yv[vv] = yp[(size_t)vv*C4];
            }
            #pragma unroll
            for (int uu=0; uu<N; ++uu){
                float4 v = make_float4(0.f,0.f,0.f,0.f);
                if (valid){
                    #pragma unroll
                    for (int vv=0; vv<N; ++vv){
                        float av = sAdj[uu][vv];
                        v.x += av*yv[vv].x; v.y += av*yv[vv].y;
                        v.z += av*yv[vv].z; v.w += av*yv[vv].w;
                    }
                }
                sB4[(hb*N+uu)*PRZ + c4] = v;
            }
        }
    } else {
        for (int p=tid; p<(TBL+2)*N*C4; p+=TH){
            int c4 = p % C4, r = p / C4, uu = r % N, hb = r / N;
            int t = t0 + hb - 1;
            float4 v = make_float4(0.f,0.f,0.f,0.f);
            if (t >= 0 && t < NT)
                v = ((const float4*)(Zin + ((size_t)(bt0+hb-1)*25 + gs0+uu)*64))[c4];
            sB4[r*PRZ + c4] = v;
        }
    }

    unsigned long long acc[N][4];
    unsigned long long z2 = pk2(0.f, 0.f);
    #pragma unroll
    for (int i=0;i<N;++i)
        #pragma unroll
        for (int jp=0;jp<4;++jp) acc[i][jp]=z2;

    const float4* TWg = TWi + (size_t)g*3*WKT;
    for (int kt=0;kt<3;++kt){
        __syncthreads();
        for (int p=tid; p<WKT; p+=TH) sW4[p] = TWg[kt*WKT + p];
        __syncthreads();
        #pragma unroll 8
        for (int kk4=0;kk4<C4;++kk4)
            gemm_kk4<CT,N>(acc, sB4 + (ty + N*kt)*PRZ + kk4, TBL*PRZ,
                           sWl + 2*kk4*4*CT + tx);
    }

    if (MODE==1){
        constexpr int RPASS = CRES/64;
        constexpr int RWP   = 32*4*CT;
        const float4* RWg = RWi + (size_t)g*2048;
        for (int ph=0; ph<RPASS; ++ph){
            __syncthreads();
            for (int p=tid; p<TBL*N*16; p+=TH){
                int c4l = p % 16, r = p / 16, uu = r % N, t = r / N;
                float4 v = ((const float4*)(Yres + ((size_t)(bt0+t)*25 + gs0+uu)*CRES))[ph*16 + c4l];
                sB4[r*PRZ + c4l] = v;
            }
            for (int p=tid; p<RWP; p+=TH) sW4[p] = RWg[ph*RWP + p];
            __syncthreads();
            #pragma unroll 8
            for (int kk4l=0;kk4l<16;++kk4l)
                gemm_kk4<CT,N>(acc, sB4 + ty*PRZ + kk4l, TBL*PRZ, sWl + 2*kk4l*4*CT + tx);
        }
    }

    float cst[8], gsv[8], bbv[8];
    #pragma unroll
    for (int jp=0;jp<4;++jp){
        int oa = tx + CT*2*jp;
        cst[2*jp]   = CST[g*COUT+oa];       cst[2*jp+1] = CST[g*COUT+oa+CT];
        gsv[2*jp]   = GS [g*COUT+oa]*BNS;   gsv[2*jp+1] = GS [g*COUT+oa+CT]*BNS;
        bbv[2*jp]   = BB [g*COUT+oa];       bbv[2*jp+1] = BB [g*COUT+oa+CT];
    }
    float part[8];
    #pragma unroll
    for (int q=0;q<8;++q) part[q]=0.f;
    #pragma unroll
    for (int i=0;i<N;++i){
        int r = ty+TBL*i, t = r/N, u = r%N;
        size_t base = ((size_t)(bt0+t)*25 + gs0+u)*COUT;
        int tg = t0 + t;
        bool e0 = (tg==0), e2 = (tg==NT-1);
        const float* xr = EMB ? (sX + ((t+1)*N+u)*3) : (const float*)0;
        float x0=0.f,x1=0.f,x2=0.f;
        if (EMB){ x0=xr[0]; x1=xr[1]; x2=xr[2]; }
        #pragma unroll
        for (int jp=0;jp<4;++jp){
            float lo,hi; unpk(acc[i][jp], lo, hi);
            int oa = tx + CT*2*jp;
            int ob = oa + CT;
            float pa = lo + cst[2*jp];
            float pb = hi + cst[2*jp+1];
            if (e0){ pa -= BB0[g*COUT+oa]; pb -= BB0[g*COUT+ob]; }
            if (e2){ pa -= BB2[g*COUT+oa]; pb -= BB2[g*COUT+ob]; }
            if (MODE==0){
                if (EMB){
                    pa += fmaf(x2,sEW[oa*3+2], fmaf(x1,sEW[oa*3+1], fmaf(x0,sEW[oa*3+0], sEB[oa])));
                    pb += fmaf(x2,sEW[ob*3+2], fmaf(x1,sEW[ob*3+1], fmaf(x0,sEW[ob*3+0], sEB[ob])));
                } else {
                    pa += Yres[base+oa]; pb += Yres[base+ob];
                }
            }
            float ra = fmaxf(pa*gsv[2*jp]   + bbv[2*jp],   0.f);
            float rb = fmaxf(pb*gsv[2*jp+1] + bbv[2*jp+1], 0.f);
            Yout[base+oa] = ra;
            Yout[base+ob] = rb;
            if (PSUM){ part[2*jp] += ra; part[2*jp+1] += rb; }
        }
    }
    if (PSUM){
        float* sP = (float*)sB4;
        __syncthreads();
        #pragma unroll
        for (int jp=0;jp<4;++jp){
            int oa = tx + CT*2*jp;
            sP[ty*64 + oa]      = part[2*jp];
            sP[ty*64 + oa + CT] = part[2*jp+1];
        }
        __syncthreads();
        if (tid < 64){
            float s = 0.f;
            #pragma unroll
            for (int yy=0; yy<TBL; ++yy) s += sP[yy*64 + tid];
            int b    = bt0 / NT;
            int tile = t0 / TBL;
            g_psum[(((size_t)g*64 + b)*(NT/TBL) + tile)*64 + tid] = s;
        }
    }
}

template<int COUT,int CRES,int MODE,int GCONV,int EMB,int PSUM,int TBL>
__global__ __launch_bounds__((COUT/8)*TBL)
void k_tconv(const float* __restrict__ Zin, const float* __restrict__ Yres,
             float* __restrict__ Yout,
             const float4* __restrict__ TWi, const float4* __restrict__ RWi,
             const float* __restrict__ CST, const float* __restrict__ BB0,
             const float* __restrict__ BB2,
             const float* __restrict__ GS, const float* __restrict__ BB,
             const float* __restrict__ EW, const float* __restrict__ EB)
{
    extern __shared__ float sm[];
    int g = blockIdx.y;
    if (g == 0)
        tconv_body<COUT,CRES,MODE,GCONV,EMB,PSUM,TBL,5>(Zin,Yres,Yout,TWi,RWi,CST,BB0,BB2,GS,BB,EW,EB,0,sm);
    else if (g <= 2)
        tconv_body<COUT,CRES,MODE,GCONV,EMB,PSUM,TBL,6>(Zin,Yres,Yout,TWi,RWi,CST,BB0,BB2,GS,BB,EW,EB,g,sm);
    else
        tconv_body<COUT,CRES,MODE,GCONV,EMB,PSUM,TBL,4>(Zin,Yres,Yout,TWi,RWi,CST,BB0,BB2,GS,BB,EW,EB,g,sm);
}

// fused feature-mean (from psum) + VQ
__global__ __launch_bounds__(128) void k_featvq(const float* __restrict__ cb,
                                                float* __restrict__ out)
{
    int g = blockIdx.x, b = blockIdx.y;
    int tid = threadIdx.x;
    int n = c_gn[g];
    __shared__ float f[64];
    if (tid < 64){
        const float* pp = g_psum + (((size_t)g*64 + b)*16)*64 + tid;
        float s = 0.f;
        #pragma unroll
        for (int tile=0; tile<16; ++tile) s += pp[tile*64];
        f[tid] = s / (float)(NT*n);
    }
    __syncthreads();

    __shared__ float ds[128];
    __shared__ int   sidx;
    {
        const float* ck = cb + (g*128 + tid)*64;
        float dot=0.f, scb=0.f;
        for (int oo=0;oo<64;++oo){ dot += f[oo]*ck[oo]; scb += ck[oo]*ck[oo]; }
        ds[tid] = scb - 2.f*dot;
    }
    __syncthreads();
    if (tid==0){
        float best = ds[0]; int bi = 0;
        for (int kk=1;kk<128;++kk) if (ds[kk] < best){ best = ds[kk]; bi = kk; }
        sidx = bi;
    }
    __syncthreads();
    int idx = sidx;
    __shared__ float dsq[64];
    if (tid < 64){
        float q = cb[(g*128 + idx)*64 + tid];
        out[(g*64+b)*64 + tid] = q;
        float dd = q - f[tid];
        dsq[tid] = dd*dd;
    }
    __syncthreads();
    if (tid==0){
        float ss=0.f;
        for (int oo=0;oo<64;++oo) ss += dsq[oo];
        g_loss[g*64+b] = 1.25f * ss / 4096.f;
        out[5*64*64 + 1 + g*64 + b] = (float)idx;
    }
}

__global__ void k_lred(float* out){
    __shared__ float s[320];
    int t = threadIdx.x;
    if (t < 320) s[t] = g_loss[t];
    __syncthreads();
    if (t==0){
        float a=0.f;
        for (int i=0;i<320;i++) a += s[i];
        out[5*64*64] = a;
    }
}

extern "C" void kernel_launch(void* const* d_in, const int* in_sizes, int n_in,
                              void* d_out, int out_size)
{
    const float* x        = (const float*)d_in[0];
    const float* embed_w  = (const float*)d_in[1];
    const float* embed_b  = (const float*)d_in[2];
    const float* sgcn_w1  = (const float*)d_in[3];
    const float* sgcn_b1  = (const float*)d_in[4];
    const float* tconv_w1 = (const float*)d_in[5];
    const float* tconv_b1 = (const float*)d_in[6];
    const float* bn_g1    = (const float*)d_in[7];
    const float* bn_b1    = (const float*)d_in[8];
    const float* res_w2   = (const float*)d_in[9];
    const float* res_b2   = (const float*)d_in[10];
    const float* resbn_g2 = (const float*)d_in[11];
    const float* resbn_b2 = (const float*)d_in[12];
    const float* sgcn_w2  = (const float*)d_in[13];
    const float* sgcn_b2  = (const float*)d_in[14];
    const float* tconv_w2 = (const float*)d_in[15];
    const float* tconv_b2 = (const float*)d_in[16];
    const float* bn_g2    = (const float*)d_in[17];
    const float* bn_b2    = (const float*)d_in[18];
    const float* res_w3   = (const float*)d_in[19];
    const float* res_b3   = (const float*)d_in[20];
    const float* resbn_g3 = (const float*)d_in[21];
    const float* resbn_b3 = (const float*)d_in[22];
    const float* sgcn_w3  = (const float*)d_in[23];
    const float* sgcn_b3  = (const float*)d_in[24];
    const float* tconv_w3 = (const float*)d_in[25];
    const float* tconv_b3 = (const float*)d_in[26];
    const float* bn_g3    = (const float*)d_in[27];
    const float* bn_b3    = (const float*)d_in[28];
    const float* codebooks= (const float*)d_in[29];
    float* out = (float*)d_out;

    void *vp;
    #define SYM(name, s, T) cudaGetSymbolAddress(&vp, s); T* name = (T*)vp;
    SYM(pZ, g_Z, float)  SYM(pY1, g_Y1, float)
    SYM(pY2, g_Y2, float)  SYM(pY3, g_Y3, float)
    SYM(pSB3,g_sb3,float)
    SYM(pC1, g_cst1,float) SYM(pB01,g_bb0_1,float) SYM(pB21,g_bb2_1,float)
    SYM(pC2, g_cst2,float) SYM(pB02,g_bb0_2,float) SYM(pB22,g_bb2_2,float)
    SYM(pC3, g_cst3,float) SYM(pZERO,g_zero,float)
    SYM(pSW3,g_sw3i,float4)
    SYM(pRW2,g_rw2i,float4) SYM(pRW3,g_rw3i,float4)
    SYM(pTW1,g_tw1i,float4) SYM(pTW2,g_tw2i,float4) SYM(pTW3,g_tw3i,float4)
    #undef SYM

    dim3 grid16(BT/16, 5);
    dim3 grid8 (BT/8,  5);

    size_t sm_t1 = (size_t)(18*6*17 + 1024)*16 + (18*6*3 + 192 + 64)*4;  // ~49.4 KB
    size_t sm_t2 = (size_t)(10*6*17 + 2048)*16;                          // 49.1 KB
    size_t sm_t3 = (size_t)(18*6*17 + 1024)*16;                          // 45.8 KB
    size_t sm_g3 = (size_t)(16*6*17 + 1024)*16;                          // 42.6 KB

    cudaFuncSetAttribute((k_tconv<64,64,0,1,1,0,16>),  cudaFuncAttributeMaxDynamicSharedMemorySize, (int)sm_t1);
    cudaFuncSetAttribute((k_tconv<128,64,1,1,0,0,8>),  cudaFuncAttributeMaxDynamicSharedMemorySize, (int)sm_t2);
    cudaFuncSetAttribute(k_gcn3,                       cudaFuncAttributeMaxDynamicSharedMemorySize, (int)sm_g3);
    cudaFuncSetAttribute((k_tconv<64,128,1,0,0,1,16>), cudaFuncAttributeMaxDynamicSharedMemorySize, (int)sm_t3);

    k_prep0<<<32,256>>>(sgcn_w1, sgcn_w2);
    k_prep<<<64,256>>>(sgcn_w1, sgcn_b1, tconv_w1, tconv_b1,
                       res_w2, res_b2, resbn_g2, resbn_b2, sgcn_w2, sgcn_b2, tconv_w2, tconv_b2,
                       res_w3, res_b3, resbn_g3, resbn_b3, sgcn_w3, sgcn_b3, tconv_w3, tconv_b3);

    k_tconv<64,64,0,1,1,0,16><<<grid16,128,sm_t1>>>(x, x, pY1, pTW1, pRW2,
                                               pC1, pB01, pB21, bn_g1, bn_b1, embed_w, embed_b);
    k_tconv<128,64,1,1,0,0,8><<<grid8,128,sm_t2>>>(pY1, pY1, pY2, pTW2, pRW2,
                                                pC2, pB02, pB22, bn_g2, bn_b2, nullptr, nullptr);
    k_gcn3<<<grid16,128,sm_g3>>>(pY2, pZ, pSW3, pSB3);
    k_tconv<64,128,1,0,0,1,16><<<grid16,128,sm_t3>>>(pZ, pY2, pY3, pTW3, pRW3,
                                                pC3, pZERO, pZERO, bn_g3, bn_b3, nullptr, nullptr);

    k_featvq<<<dim3(5,64),128>>>(codebooks, out);
    k_lred<<<1,512>>>(out);
}